// round 13
// baseline (speedup 1.0000x reference)
#include <cuda_runtime.h>
#include <cuda_fp16.h>
#include <cstdint>

// ---------------- problem constants ----------------
#define S_IMG 1024
#define S_TXT 512
#define S_TOT 1536
#define NH    24
#define HD    128
#define HID   3072
#define IPD   2048
#define LIP   16
#define EPS_F 1e-6f
#define SM_SCALE 0.08838834764831845f  // 1/sqrt(128)

// ---------------- fp32 scratch ----------------
__device__ float g_q [S_IMG * HID];
__device__ float g_k [S_IMG * HID];
__device__ float g_v [S_IMG * HID];
__device__ float g_eq[S_TXT * HID];
__device__ float g_ek[S_TXT * HID];
__device__ float g_ev[S_TXT * HID];
__device__ float g_ipk[LIP * HID];
__device__ float g_ipv[LIP * HID];

// fp16 q (hi/lo, pre-scaled) + k/v (single) in [H][S][D] — attention path
__device__ __align__(16) __half g_aqh[(size_t)NH * S_TOT * HD], g_aql[(size_t)NH * S_TOT * HD];
__device__ __align__(16) __half g_akh[(size_t)NH * S_TOT * HD];
__device__ __align__(16) __half g_avh[(size_t)NH * S_TOT * HD];

// ---------------- fp16 activations (hi only) ----------------
__device__ __align__(16) __half g_hs_h [S_IMG * HID];
__device__ __align__(16) __half g_enc_h[S_TXT * HID];
__device__ __align__(16) __half g_iph_h[LIP * IPD];
__device__ __align__(16) __half g_ctxh [S_TOT * HID];
// transposed weights [N][K] fp16
__device__ __align__(16) __half g_WqT [HID * HID];
__device__ __align__(16) __half g_WkT [HID * HID];
__device__ __align__(16) __half g_WvT [HID * HID];
__device__ __align__(16) __half g_WaqT[HID * HID];
__device__ __align__(16) __half g_WakT[HID * HID];
__device__ __align__(16) __half g_WavT[HID * HID];
__device__ __align__(16) __half g_WoT [HID * HID];
__device__ __align__(16) __half g_WadT[HID * HID];
__device__ __align__(16) __half g_WkiT[HID * IPD];
__device__ __align__(16) __half g_WviT[HID * IPD];

// ---------------- low-level helpers ----------------
__device__ __forceinline__ uint32_t smem_u32(const void* p) {
    return (uint32_t)__cvta_generic_to_shared(p);
}
__device__ __forceinline__ void cpa16(uint32_t dst, const void* src, int sz) {
    asm volatile("cp.async.cg.shared.global [%0], [%1], 16, %2;"
                 :: "r"(dst), "l"(src), "r"(sz) : "memory");
}
__device__ __forceinline__ void cp_commit() {
    asm volatile("cp.async.commit_group;" ::: "memory");
}
template<int N> __device__ __forceinline__ void cp_wait() {
    asm volatile("cp.async.wait_group %0;" :: "n"(N) : "memory");
}
__device__ __forceinline__ void ldsm4(uint32_t* r, uint32_t addr) {
    asm volatile("ldmatrix.sync.aligned.m8n8.x4.shared.b16 {%0,%1,%2,%3}, [%4];"
                 : "=r"(r[0]), "=r"(r[1]), "=r"(r[2]), "=r"(r[3]) : "r"(addr));
}
__device__ __forceinline__ void ldsm4t(uint32_t* r, uint32_t addr) {
    asm volatile("ldmatrix.sync.aligned.m8n8.x4.trans.shared.b16 {%0,%1,%2,%3}, [%4];"
                 : "=r"(r[0]), "=r"(r[1]), "=r"(r[2]), "=r"(r[3]) : "r"(addr));
}
__device__ __forceinline__ void mma_f16(float* c, const uint32_t* a, uint32_t b0, uint32_t b1) {
    asm volatile(
        "mma.sync.aligned.m16n8k16.row.col.f32.f16.f16.f32 "
        "{%0,%1,%2,%3}, {%4,%5,%6,%7}, {%8,%9}, {%0,%1,%2,%3};"
        : "+f"(c[0]), "+f"(c[1]), "+f"(c[2]), "+f"(c[3])
        : "r"(a[0]), "r"(a[1]), "r"(a[2]), "r"(a[3]), "r"(b0), "r"(b1));
}
__device__ __forceinline__ uint32_t packhf(float a, float b) {
    __half2 t = __floats2half2_rn(a, b);
    return *(uint32_t*)&t;
}

// ---------------- GEMM: C = A @ WT^T + bias (1-term fp16 A) ----------------
struct GemmSet {
    const __half* Ah;                      // [M][K]
    const __half* WT;                      // [HID][K]  (pre-transposed)
    const float*  bias; float* out;        // out [M][HID]
    int M; int K;
};

#define GTILE 18432                   // 128 rows * 144B (72 halfs, 64 used)
#define GSTAGE (2 * GTILE)
#define GEMM_SMEM (2 * GSTAGE)        // 73728

__global__ __launch_bounds__(256) void gemm_mma(GemmSet s0, GemmSet s1, GemmSet s2)
{
    extern __shared__ char smem[];
    const uint32_t sb = smem_u32(smem);
    const int tid = threadIdx.x, warp = tid >> 5, lane = tid & 31;
    const GemmSet S = (blockIdx.z == 0) ? s0 : ((blockIdx.z == 1) ? s1 : s2);
    const int nb = blockIdx.x, mb = blockIdx.y;
    if (mb * 128 >= S.M) return;
    const int wm = warp & 3, wn = warp >> 2;
    const int K = S.K;

    const __half* gAh = S.Ah + (size_t)mb * 128 * K;
    const __half* gB  = S.WT + (size_t)nb * 128 * K;
    const int rows_a = min(128, S.M - mb * 128);

    auto issue = [&](int kc, int st) {
        uint32_t base = sb + st * GSTAGE;
#pragma unroll
        for (int p = 0; p < 4; p++) {
            int idx = tid + p * 256;       // 0..1023
            int row = idx >> 3, ch = idx & 7;
            bool v = row < rows_a;
            int sz = v ? 16 : 0;
            size_t go = (size_t)row * K + (size_t)kc * 64 + ch * 8;
            uint32_t d = base + (uint32_t)(row * 144 + ch * 16);
            cpa16(d,         v ? (gAh + go) : gAh, sz);
            cpa16(d + GTILE, gB + go, 16);
        }
        cp_commit();
    };

    float c[2][8][4];
#pragma unroll
    for (int i = 0; i < 2; i++)
#pragma unroll
        for (int j = 0; j < 8; j++)
#pragma unroll
            for (int e = 0; e < 4; e++) c[i][j][e] = 0.f;

    const int nch = K / 64;
    issue(0, 0);

    const int a_r  = wm * 32 + (lane & 15);
    const int a_c8 = (lane >> 4) * 8;
    const int b_n  = wn * 64 + (lane >> 4) * 8 + (lane & 7);
    const int b_c8 = ((lane >> 3) & 1) * 8;

    for (int kc = 0; kc < nch; kc++) {
        const int st = kc & 1;
        if (kc + 1 < nch) { issue(kc + 1, st ^ 1); cp_wait<1>(); }
        else              { cp_wait<0>(); }
        __syncthreads();

        const uint32_t sa = sb + st * GSTAGE;
#pragma unroll
        for (int ks = 0; ks < 4; ks++) {
            uint32_t ah[2][4];
#pragma unroll
            for (int mf = 0; mf < 2; mf++) {
                uint32_t ad = sa + (uint32_t)((a_r + mf * 16) * 144 + (ks * 16 + a_c8) * 2);
                ldsm4(ah[mf], ad);
            }
            uint32_t bh[8][2];
#pragma unroll
            for (int nf = 0; nf < 4; nf++) {
                uint32_t bd = sa + GTILE +
                              (uint32_t)((b_n + nf * 16) * 144 + (ks * 16 + b_c8) * 2);
                uint32_t t0[4];
                ldsm4(t0, bd);
                bh[nf * 2][0] = t0[0]; bh[nf * 2][1] = t0[1];
                bh[nf * 2 + 1][0] = t0[2]; bh[nf * 2 + 1][1] = t0[3];
            }
#pragma unroll
            for (int mf = 0; mf < 2; mf++)
#pragma unroll
                for (int nf = 0; nf < 8; nf++)
                    mma_f16(c[mf][nf], ah[mf], bh[nf][0], bh[nf][1]);
        }
        __syncthreads();
    }

#pragma unroll
    for (int mf = 0; mf < 2; mf++) {
#pragma unroll
        for (int nf = 0; nf < 8; nf++) {
            int row0 = mb * 128 + wm * 32 + mf * 16 + (lane >> 2);
            int col  = nb * 128 + wn * 64 + nf * 8 + (lane & 3) * 2;
            float b0 = S.bias[col], b1 = S.bias[col + 1];
            if (row0 < S.M) {
                float2 o0 = make_float2(c[mf][nf][0] + b0, c[mf][nf][1] + b1);
                *(float2*)(S.out + (size_t)row0 * HID + col) = o0;
            }
            int row1 = row0 + 8;
            if (row1 < S.M) {
                float2 o1 = make_float2(c[mf][nf][2] + b0, c[mf][nf][3] + b1);
                *(float2*)(S.out + (size_t)row1 * HID + col) = o1;
            }
        }
    }
}

// ---------------- flash attention, fp16 (Q hi/lo; K,V single; P single) ----------------
// Epilogue writes fp16 ctx (hi only).
#define APITCH 272
#define AQ_H   0
#define AQ_L   34816
#define AST0   69632
#define AKV_V  17408
#define ASTAGE 34816
#define ATTN_SMEM (AST0 + 2 * ASTAGE)   // 139264

__global__ __launch_bounds__(256) void attn_mma(
    const __half* __restrict__ Qh, const __half* __restrict__ Ql,
    const __half* __restrict__ Kh, const __half* __restrict__ Vh,
    __half* __restrict__ cxh)
{
    extern __shared__ char smem[];
    const uint32_t sb = smem_u32(smem);
    const int tid = threadIdx.x, w = tid >> 5, lane = tid & 31;
    const int mb = blockIdx.x, h = blockIdx.y;
    const size_t hbase = (size_t)h * S_TOT * HD;

#pragma unroll
    for (int i = 0; i < 8; i++) {
        int c = tid + i * 256;
        int row = c >> 4, ch = c & 15;
        size_t g = hbase + (size_t)(mb * 128 + row) * HD + ch * 8;
        *(uint4*)(smem + AQ_H + row * APITCH + ch * 16) = *(const uint4*)(Qh + g);
        *(uint4*)(smem + AQ_L + row * APITCH + ch * 16) = *(const uint4*)(Ql + g);
    }

    auto issueKV = [&](int t, int st) {
        uint32_t base = sb + AST0 + st * ASTAGE;
        int key0 = t * 64;
#pragma unroll
        for (int i = 0; i < 4; i++) {
            int c = tid + i * 256;
            int row = c >> 4, ch = c & 15;
            size_t g = hbase + (size_t)(key0 + row) * HD + ch * 8;
            uint32_t d = base + row * APITCH + ch * 16;
            cpa16(d,         Kh + g, 16);
            cpa16(d + AKV_V, Vh + g, 16);
        }
        cp_commit();
    };

    float co[16][4];
#pragma unroll
    for (int i = 0; i < 16; i++)
#pragma unroll
        for (int e = 0; e < 4; e++) co[i][e] = 0.f;
    float m0 = -1e30f, m1 = -1e30f, l0 = 0.f, l1 = 0.f;

    const uint32_t qa_ro = (uint32_t)((w * 16 + (lane & 15)) * APITCH + ((lane >> 4) * 8) * 2);
    const int b_n  = (lane >> 4) * 8 + (lane & 7);
    const int b_c8 = ((lane >> 3) & 1) * 8;
    const uint32_t vt_ro = (uint32_t)((lane & 15) * APITCH + ((lane >> 4) * 8) * 2);

    issueKV(0, 0);

    const int NT = S_TOT / 64;
    for (int t = 0; t < NT; t++) {
        const int st = t & 1;
        if (t + 1 < NT) { issueKV(t + 1, st ^ 1); cp_wait<1>(); }
        else            { cp_wait<0>(); }
        __syncthreads();

        const uint32_t kbase = sb + AST0 + st * ASTAGE;

        float cs[8][4];
#pragma unroll
        for (int i = 0; i < 8; i++)
#pragma unroll
            for (int e = 0; e < 4; e++) cs[i][e] = 0.f;

#pragma unroll
        for (int kt = 0; kt < 8; kt++) {
            uint32_t ah[4], al[4];
            uint32_t qa = sb + qa_ro + (uint32_t)(kt * 32);
            ldsm4(ah, qa + AQ_H);
            ldsm4(al, qa + AQ_L);
#pragma unroll
            for (int nfp = 0; nfp < 4; nfp++) {
                uint32_t bd = kbase + (uint32_t)((b_n + nfp * 16) * APITCH + (kt * 16 + b_c8) * 2);
                uint32_t t0[4];
                ldsm4(t0, bd);
                mma_f16(cs[nfp * 2],     ah, t0[0], t0[1]);
                mma_f16(cs[nfp * 2 + 1], ah, t0[2], t0[3]);
                mma_f16(cs[nfp * 2],     al, t0[0], t0[1]);
                mma_f16(cs[nfp * 2 + 1], al, t0[2], t0[3]);
            }
        }

        float mx0 = m0, mx1 = m1;
#pragma unroll
        for (int nf = 0; nf < 8; nf++) {
            mx0 = fmaxf(mx0, fmaxf(cs[nf][0], cs[nf][1]));
            mx1 = fmaxf(mx1, fmaxf(cs[nf][2], cs[nf][3]));
        }
        mx0 = fmaxf(mx0, __shfl_xor_sync(0xffffffffu, mx0, 1));
        mx0 = fmaxf(mx0, __shfl_xor_sync(0xffffffffu, mx0, 2));
        mx1 = fmaxf(mx1, __shfl_xor_sync(0xffffffffu, mx1, 1));
        mx1 = fmaxf(mx1, __shfl_xor_sync(0xffffffffu, mx1, 2));
        float corr0 = __expf(m0 - mx0), corr1 = __expf(m1 - mx1);
        m0 = mx0; m1 = mx1;

        float rs0 = 0.f, rs1 = 0.f;
        uint32_t ph[4][4];
#pragma unroll
        for (int kt = 0; kt < 4; kt++) {
#pragma unroll
            for (int hh = 0; hh < 2; hh++) {
                int nf = 2 * kt + hh;
                float p0 = __expf(cs[nf][0] - m0), p1 = __expf(cs[nf][1] - m0);
                float p2 = __expf(cs[nf][2] - m1), p3 = __expf(cs[nf][3] - m1);
                rs0 += p0 + p1; rs1 += p2 + p3;
                ph[kt][hh * 2]     = packhf(p0, p1);
                ph[kt][hh * 2 + 1] = packhf(p2, p3);
            }
        }
        rs0 += __shfl_xor_sync(0xffffffffu, rs0, 1);
        rs0 += __shfl_xor_sync(0xffffffffu, rs0, 2);
        rs1 += __shfl_xor_sync(0xffffffffu, rs1, 1);
        rs1 += __shfl_xor_sync(0xffffffffu, rs1, 2);
        l0 = l0 * corr0 + rs0;
        l1 = l1 * corr1 + rs1;

#pragma unroll
        for (int nf = 0; nf < 16; nf++) {
            co[nf][0] *= corr0; co[nf][1] *= corr0;
            co[nf][2] *= corr1; co[nf][3] *= corr1;
        }

        const uint32_t vbase = kbase + AKV_V;
#pragma unroll
        for (int kt = 0; kt < 4; kt++) {
#pragma unroll
            for (int np = 0; np < 8; np++) {
                uint32_t vd = vbase + vt_ro + (uint32_t)(kt * 16 * APITCH + np * 32);
                uint32_t th[4];
                ldsm4t(th, vd);
                mma_f16(co[np * 2],     ph[kt], th[0], th[1]);
                mma_f16(co[np * 2 + 1], ph[kt], th[2], th[3]);
            }
        }
        __syncthreads();
    }

    // epilogue: write fp16 ctx (hi only)
    float i0 = 1.f / l0, i1 = 1.f / l1;
    int r0g = mb * 128 + w * 16 + (lane >> 2);
#pragma unroll
    for (int nf = 0; nf < 16; nf++) {
        int col = h * HD + nf * 8 + (lane & 3) * 2;
        *(__half2*)(cxh + (size_t)r0g * HID + col) =
            __floats2half2_rn(co[nf][0] * i0, co[nf][1] * i0);
        *(__half2*)(cxh + (size_t)(r0g + 8) * HID + col) =
            __floats2half2_rn(co[nf][2] * i1, co[nf][3] * i1);
    }
}

// ---------------- fp32 -> fp16 (hi only) ----------------
__global__ __launch_bounds__(256) void conv_h(
    const float* __restrict__ x, __half* __restrict__ h, int n4)
{
    int i = blockIdx.x * 256 + threadIdx.x;
    if (i >= n4) return;
    float4 v = ((const float4*)x)[i];
    ((__half2*)h)[2 * i]     = __floats2half2_rn(v.x, v.y);
    ((__half2*)h)[2 * i + 1] = __floats2half2_rn(v.z, v.w);
}

// ---------------- W[K][N] fp32 -> W^T[N][K] fp16, batched by z ----------------
struct WTask { const float* W; __half* T; };

__global__ __launch_bounds__(256) void conv_wT(
    WTask t0, WTask t1, WTask t2, int K, int N)
{
    __shared__ float s[32][33];
    const WTask T = (blockIdx.z == 0) ? t0 : ((blockIdx.z == 1) ? t1 : t2);
    const int tx = threadIdx.x & 31, ty = threadIdx.x >> 5;
    const int k0 = blockIdx.y * 32, n0 = blockIdx.x * 32;
#pragma unroll
    for (int r = 0; r < 4; r++)
        s[ty + r * 8][tx] = T.W[(size_t)(k0 + ty + r * 8) * N + n0 + tx];
    __syncthreads();
#pragma unroll
    for (int r = 0; r < 4; r++) {
        int n = n0 + ty + r * 8, k = k0 + tx;
        T.T[(size_t)n * K + k] = __float2half_rn(s[tx][ty + r * 8]);
    }
}

// ---------------- prepare: rms + rope + head layout -> fp16 ----------------
__global__ __launch_bounds__(128) void prepare_qkv(
    const float* __restrict__ q,  const float* __restrict__ k,  const float* __restrict__ v,
    const float* __restrict__ eq, const float* __restrict__ ek, const float* __restrict__ ev,
    const float* __restrict__ nq, const float* __restrict__ nk,
    const float* __restrict__ naq,const float* __restrict__ nak,
    const float* __restrict__ cosr, const float* __restrict__ sinr,
    __half* __restrict__ qh, __half* __restrict__ ql,
    __half* __restrict__ kh, __half* __restrict__ vh)
{
    const int s = blockIdx.x;
    const int h = blockIdx.y;
    const int d = threadIdx.x;
    const int col = h * HD + d;

    const float *sq, *sk, *sv, *wq, *wk;
    if (s < S_TXT) {
        sq = eq + (size_t)s * HID; sk = ek + (size_t)s * HID; sv = ev + (size_t)s * HID;
        wq = naq; wk = nak;
    } else {
        int si = s - S_TXT;
        sq = q + (size_t)si * HID; sk = k + (size_t)si * HID; sv = v + (size_t)si * HID;
        wq = nq; wk = nk;
    }
    float xq = sq[col], xk = sk[col], xv = sv[col];

    __shared__ float red[8];
    float s2q = xq * xq, s2k = xk * xk;
#pragma unroll
    for (int o = 16; o; o >>= 1) {
        s2q += __shfl_xor_sync(0xffffffffu, s2q, o);
        s2k += __shfl_xor_sync(0xffffffffu, s2k, o);
    }
    int wid = d >> 5, lid = d & 31;
    if (lid == 0) { red[wid] = s2q; red[4 + wid] = s2k; }
    __syncthreads();
    float tq = red[0] + red[1] + red[2] + red[3];
    float tk = red[4] + red[5] + red[6] + red[7];
    float rq = rsqrtf(tq / (float)HD + EPS_F);
    float rk = rsqrtf(tk / (float)HD + EPS_F);
    float nxq = xq * rq * wq[d];
    float nxk = xk * rk * wk[d];

    __shared__ float shq[128], shk[128];
    shq[d] = nxq; shk[d] = nxk;
    __syncthreads();

    float c  = cosr[(size_t)s * HD + d];
    float sn = sinr[(size_t)s * HD + d];
    float oq, ok;
    if ((d & 1) == 0) {
        oq = nxq * c - shq[d + 1] * sn;
        ok = nxk * c - shk[d + 1] * sn;
    } else {
        oq = nxq * c + shq[d - 1] * sn;
        ok = nxk * c + shk[d - 1] * sn;
    }
    oq *= SM_SCALE;

    size_t o = ((size_t)h * S_TOT + s) * HD + d;
    __half hq = __float2half_rn(oq);
    qh[o] = hq;
    ql[o] = __float2half_rn(oq - __half2float(hq));
    kh[o] = __float2half_rn(ok);
    vh[o] = __float2half_rn(xv);
}

// ---------------- IP attention: RMW on fp16 ctx (hi only) ----------------
__global__ __launch_bounds__(256) void ip_attn(
    const float* __restrict__ q, const float* __restrict__ ipk, const float* __restrict__ ipv,
    const float* __restrict__ wqn, const float* __restrict__ wkn,
    __half* __restrict__ cxh)
{
    __shared__ float sK[LIP * HD];
    __shared__ float sV[LIP * HD];
    const int t = threadIdx.x, h = blockIdx.y;
    const int w = t >> 5, lane = t & 31;

#pragma unroll
    for (int i = 0; i < 8; i++) {
        int idx = t + i * 256;
        int r = idx >> 7, c = idx & 127;
        sK[idx] = ipk[(size_t)r * HID + h * HD + c];
        sV[idx] = ipv[(size_t)r * HID + h * HD + c];
    }
    __syncthreads();

    float4 wk4 = *(const float4*)(wkn + lane * 4);
    for (int rr = w; rr < LIP; rr += 8) {
        float4 kv = ((float4*)sK)[rr * 32 + lane];
        float ss = kv.x * kv.x + kv.y * kv.y + kv.z * kv.z + kv.w * kv.w;
#pragma unroll
        for (int o = 16; o; o >>= 1) ss += __shfl_xor_sync(0xffffffffu, ss, o);
        float r = rsqrtf(ss / (float)HD + EPS_F);
        kv.x *= r * wk4.x; kv.y *= r * wk4.y; kv.z *= r * wk4.z; kv.w *= r * wk4.w;
        ((float4*)sK)[rr * 32 + lane] = kv;
    }
    __syncthreads();

    const int s = blockIdx.x * 8 + w;
    float4 q4 = *(const float4*)(q + (size_t)s * HID + h * HD + lane * 4);
    float ss = q4.x * q4.x + q4.y * q4.y + q4.z * q4.z + q4.w * q4.w;
#pragma unroll
    for (int o = 16; o; o >>= 1) ss += __shfl_xor_sync(0xffffffffu, ss, o);
    float rq = rsqrtf(ss / (float)HD + EPS_F);
    float4 wq4 = *(const float4*)(wqn + lane * 4);
    q4.x *= rq * wq4.x; q4.y *= rq * wq4.y; q4.z *= rq * wq4.z; q4.w *= rq * wq4.w;

    float sc[LIP];
#pragma unroll
    for (int j = 0; j < LIP; j++) {
        float4 kv = ((const float4*)sK)[j * 32 + lane];
        float d = q4.x * kv.x + q4.y * kv.y + q4.z * kv.z + q4.w * kv.w;
#pragma unroll
        for (int o = 16; o; o >>= 1) d += __shfl_xor_sync(0xffffffffu, d, o);
        sc[j] = d * SM_SCALE;
    }
    float mx = sc[0];
#pragma unroll
    for (int j = 1; j < LIP; j++) mx = fmaxf(mx, sc[j]);
    float l = 0.f;
#pragma unroll
    for (int j = 0; j < LIP; j++) { sc[j] = __expf(sc[j] - mx); l += sc[j]; }
    float inv = 1.f / l;

    float4 acc = make_float4(0.f, 0.f, 0.f, 0.f);
#pragma unroll
    for (int j = 0; j < LIP; j++) {
        float p = sc[j] * inv;
        float4 vv = ((const float4*)sV)[j * 32 + lane];
        acc.x += p * vv.x; acc.y += p * vv.y; acc.z += p * vv.z; acc.w += p * vv.w;
    }

    size_t o = (size_t)(S_TXT + s) * HID + h * HD + lane * 4;
    __half2 h01 = *(__half2*)(cxh + o), h23 = *(__half2*)(cxh + o + 2);
    *(__half2*)(cxh + o) =
        __floats2half2_rn(__half2float(h01.x) + acc.x, __half2float(h01.y) + acc.y);
    *(__half2*)(cxh + o + 2) =
        __floats2half2_rn(__half2float(h23.x) + acc.z, __half2float(h23.y) + acc.w);
}

// ---------------- host launch ----------------
static float* symf(const void* s) { void* p = nullptr; cudaGetSymbolAddress(&p, s); return (float*)p; }
static __half* symh(const void* s) { void* p = nullptr; cudaGetSymbolAddress(&p, s); return (__half*)p; }

extern "C" void kernel_launch(void* const* d_in, const int* in_sizes, int n_in,
                              void* d_out, int out_size)
{
    const float* hs    = (const float*)d_in[0];
    const float* enc   = (const float*)d_in[1];
    const float* iph   = (const float*)d_in[2];
    const float* rcos  = (const float*)d_in[3];
    const float* rsin  = (const float*)d_in[4];
    const float* Wq    = (const float*)d_in[5];
    const float* bq    = (const float*)d_in[6];
    const float* Wk    = (const float*)d_in[7];
    const float* bk    = (const float*)d_in[8];
    const float* Wv    = (const float*)d_in[9];
    const float* bv    = (const float*)d_in[10];
    const float* nqw   = (const float*)d_in[11];
    const float* nkw   = (const float*)d_in[12];
    const float* Waq   = (const float*)d_in[13];
    const float* baq   = (const float*)d_in[14];
    const float* Wak   = (const float*)d_in[15];
    const float* bak   = (const float*)d_in[16];
    const float* Wav   = (const float*)d_in[17];
    const float* bav   = (const float*)d_in[18];
    const float* naqw  = (const float*)d_in[19];
    const float* nakw  = (const float*)d_in[20];
    const float* Wo    = (const float*)d_in[21];
    const float* bo    = (const float*)d_in[22];
    const float* Wadd  = (const float*)d_in[23];
    const float* badd  = (const float*)d_in[24];
    const float* Wkip  = (const float*)d_in[25];
    const float* bkip  = (const float*)d_in[26];
    const float* Wvip  = (const float*)d_in[27];
    const float* bvip  = (const float*)d_in[28];
    const float* nipq  = (const float*)d_in[29];
    const float* nipk  = (const float*)d_in[30];

    float* out = (float*)d_out;

    float* pq   = symf(g_q);   float* pk   = symf(g_k);   float* pv   = symf(g_v);
    float* peq  = symf(g_eq);  float* pek  = symf(g_ek);  float* pev  = symf(g_ev);
    float* pipk = symf(g_ipk); float* pipv = symf(g_ipv);

    __half *aqh = symh(g_aqh), *aql = symh(g_aql);
    __half *akh = symh(g_akh), *avh = symh(g_avh);

    __half *hsh = symh(g_hs_h);
    __half *ech = symh(g_enc_h);
    __half *iph_h = symh(g_iph_h);
    __half *cxh = symh(g_ctxh);
    __half *wqT = symh(g_WqT),  *wkT = symh(g_WkT),  *wvT = symh(g_WvT);
    __half *waqT = symh(g_WaqT), *wakT = symh(g_WakT), *wavT = symh(g_WavT);
    __half *woT = symh(g_WoT),  *wadT = symh(g_WadT);
    __half *wkiT = symh(g_WkiT), *wviT = symh(g_WviT);

    cudaFuncSetAttribute(gemm_mma, cudaFuncAttributeMaxDynamicSharedMemorySize, GEMM_SMEM);
    cudaFuncSetAttribute(attn_mma, cudaFuncAttributeMaxDynamicSharedMemorySize, ATTN_SMEM);

    dim3 wg(HID / 32, HID / 32, 3);
    dim3 wg2(HID / 32, HID / 32, 2);
    dim3 wgip(HID / 32, IPD / 32, 2);

    // L0, L1, L2
    conv_wT<<<wg, 256>>>(WTask{Wq, wqT}, WTask{Wk, wkT}, WTask{Wv, wvT}, HID, HID);
    conv_h<<<(S_IMG * HID / 4 + 255) / 256, 256>>>(hs, hsh, S_IMG * HID / 4);
    conv_wT<<<wg, 256>>>(WTask{Waq, waqT}, WTask{Wak, wakT}, WTask{Wav, wavT}, HID, HID);

    // L3: big img q/k/v GEMM (ncu capture slot)
    GemmSet sq{hsh, wqT, bq, pq, S_IMG, HID};
    GemmSet sk{hsh, wkT, bk, pk, S_IMG, HID};
    GemmSet sv{hsh, wvT, bv, pv, S_IMG, HID};
    gemm_mma<<<dim3(HID / 128, S_IMG / 128, 3), 256, GEMM_SMEM>>>(sq, sk, sv);

    // L4..L6
    conv_h<<<(S_TXT * HID / 4 + 255) / 256, 256>>>(enc, ech, S_TXT * HID / 4);
    conv_h<<<(LIP * IPD / 4 + 255) / 256, 256>>>(iph, iph_h, LIP * IPD / 4);
    conv_wT<<<wgip, 256>>>(WTask{Wkip, wkiT}, WTask{Wvip, wviT}, WTask{Wkip, wkiT}, IPD, HID);

    // L7: enc q/k/v GEMM
    GemmSet se1{ech, waqT, baq, peq, S_TXT, HID};
    GemmSet se2{ech, wakT, bak, pek, S_TXT, HID};
    GemmSet se3{ech, wavT, bav, pev, S_TXT, HID};
    gemm_mma<<<dim3(HID / 128, S_TXT / 128, 3), 256, GEMM_SMEM>>>(se1, se2, se3);

    // L8: ip k/v GEMM
    GemmSet si1{iph_h, wkiT, bkip, pipk, LIP, IPD};
    GemmSet si2{iph_h, wviT, bvip, pipv, LIP, IPD};
    gemm_mma<<<dim3(HID / 128, 1, 2), 256, GEMM_SMEM>>>(si1, si2, si1);

    // L9: output-projection weights
    conv_wT<<<wg2, 256>>>(WTask{Wo, woT}, WTask{Wadd, wadT}, WTask{Wo, woT}, HID, HID);

    // L10: rms + rope + head layout
    prepare_qkv<<<dim3(S_TOT, NH), 128>>>(pq, pk, pv, peq, pek, pev,
                                          nqw, nkw, naqw, nakw, rcos, rsin,
                                          aqh, aql, akh, avh);

    // L11, L12: attention (writes fp16 ctx), IP attention (RMW)
    attn_mma<<<dim3(S_TOT / 128, NH), 256, ATTN_SMEM>>>(aqh, aql, akh, avh, cxh);
    ip_attn<<<dim3(S_IMG / 8, NH), 256>>>(pq, pipk, pipv, nipq, nipk, cxh);

    // L13: merged output GEMMs (z=0: img via Wo, z=1: enc via Wadd), 1-term ctx
    GemmSet so{cxh + (size_t)S_TXT * HID, woT, bo, out, S_IMG, HID};
    GemmSet sa{cxh, wadT, badd, out + (size_t)S_IMG * HID, S_TXT, HID};
    gemm_mma<<<dim3(HID / 128, S_IMG / 128, 2), 256, GEMM_SMEM>>>(so, sa, so);
}

// round 14
// speedup vs baseline: 1.4829x; 1.4829x over previous
#include <cuda_runtime.h>
#include <cuda_fp16.h>
#include <cstdint>

// ---------------- problem constants ----------------
#define S_IMG 1024
#define S_TXT 512
#define S_TOT 1536
#define NH    24
#define HD    128
#define HID   3072
#define IPD   2048
#define LIP   16
#define EPS_F 1e-6f
#define SM_SCALE 0.08838834764831845f  // 1/sqrt(128)

// ---------------- fp32 scratch ----------------
__device__ float g_q [S_IMG * HID];
__device__ float g_k [S_IMG * HID];
__device__ float g_v [S_IMG * HID];
__device__ float g_eq[S_TXT * HID];
__device__ float g_ek[S_TXT * HID];
__device__ float g_ev[S_TXT * HID];
__device__ float g_ipk[LIP * HID];
__device__ float g_ipv[LIP * HID];

// fp16 q (hi/lo, pre-scaled) + k/v (single) in [H][S][D] — attention path
__device__ __align__(16) __half g_aqh[(size_t)NH * S_TOT * HD], g_aql[(size_t)NH * S_TOT * HD];
__device__ __align__(16) __half g_akh[(size_t)NH * S_TOT * HD];
__device__ __align__(16) __half g_avh[(size_t)NH * S_TOT * HD];

// ---------------- fp16 activations (hi only) ----------------
__device__ __align__(16) __half g_hs_h [S_IMG * HID];
__device__ __align__(16) __half g_enc_h[S_TXT * HID];
__device__ __align__(16) __half g_iph_h[LIP * IPD];
__device__ __align__(16) __half g_ctxh [S_TOT * HID];
__device__ __align__(16) __half g_ctxl [S_TOT * HID];   // kept for gemm_mma<true> instantiation
// transposed weights [N][K] fp16
__device__ __align__(16) __half g_WqT [HID * HID];
__device__ __align__(16) __half g_WkT [HID * HID];
__device__ __align__(16) __half g_WvT [HID * HID];
__device__ __align__(16) __half g_WaqT[HID * HID];
__device__ __align__(16) __half g_WakT[HID * HID];
__device__ __align__(16) __half g_WavT[HID * HID];
__device__ __align__(16) __half g_WoT [HID * HID];
__device__ __align__(16) __half g_WadT[HID * HID];
__device__ __align__(16) __half g_WkiT[HID * IPD];
__device__ __align__(16) __half g_WviT[HID * IPD];

// ---------------- low-level helpers ----------------
__device__ __forceinline__ uint32_t smem_u32(const void* p) {
    return (uint32_t)__cvta_generic_to_shared(p);
}
__device__ __forceinline__ void cpa16(uint32_t dst, const void* src, int sz) {
    asm volatile("cp.async.cg.shared.global [%0], [%1], 16, %2;"
                 :: "r"(dst), "l"(src), "r"(sz) : "memory");
}
__device__ __forceinline__ void cp_commit() {
    asm volatile("cp.async.commit_group;" ::: "memory");
}
template<int N> __device__ __forceinline__ void cp_wait() {
    asm volatile("cp.async.wait_group %0;" :: "n"(N) : "memory");
}
__device__ __forceinline__ void ldsm4(uint32_t* r, uint32_t addr) {
    asm volatile("ldmatrix.sync.aligned.m8n8.x4.shared.b16 {%0,%1,%2,%3}, [%4];"
                 : "=r"(r[0]), "=r"(r[1]), "=r"(r[2]), "=r"(r[3]) : "r"(addr));
}
__device__ __forceinline__ void ldsm4t(uint32_t* r, uint32_t addr) {
    asm volatile("ldmatrix.sync.aligned.m8n8.x4.trans.shared.b16 {%0,%1,%2,%3}, [%4];"
                 : "=r"(r[0]), "=r"(r[1]), "=r"(r[2]), "=r"(r[3]) : "r"(addr));
}
__device__ __forceinline__ void mma_f16(float* c, const uint32_t* a, uint32_t b0, uint32_t b1) {
    asm volatile(
        "mma.sync.aligned.m16n8k16.row.col.f32.f16.f16.f32 "
        "{%0,%1,%2,%3}, {%4,%5,%6,%7}, {%8,%9}, {%0,%1,%2,%3};"
        : "+f"(c[0]), "+f"(c[1]), "+f"(c[2]), "+f"(c[3])
        : "r"(a[0]), "r"(a[1]), "r"(a[2]), "r"(a[3]), "r"(b0), "r"(b1));
}
__device__ __forceinline__ uint32_t packhf(float a, float b) {
    __half2 t = __floats2half2_rn(a, b);
    return *(uint32_t*)&t;
}

// ---------------- GEMM: C = A @ WT^T + bias (1- or 2-term A) ----------------
struct GemmSet {
    const __half* Ah; const __half* Al;    // [M][K]  (Al unused when !TWO)
    const __half* WT;                      // [HID][K]  (pre-transposed)
    const float*  bias; float* out;        // out [M][HID]
    int M; int K;
};

#define GTILE 18432                   // 128 rows * 144B (72 halfs, 64 used)

template<bool TWO>
__global__ __launch_bounds__(256) void gemm_mma(GemmSet s0, GemmSet s1, GemmSet s2)
{
    constexpr uint32_t STG = (TWO ? 3 : 2) * GTILE;
    constexpr uint32_t BOFF = (TWO ? 2 : 1) * GTILE;
    extern __shared__ char smem[];
    const uint32_t sb = smem_u32(smem);
    const int tid = threadIdx.x, warp = tid >> 5, lane = tid & 31;
    const GemmSet S = (blockIdx.z == 0) ? s0 : ((blockIdx.z == 1) ? s1 : s2);
    const int nb = blockIdx.x, mb = blockIdx.y;
    if (mb * 128 >= S.M) return;
    const int wm = warp & 3, wn = warp >> 2;
    const int K = S.K;

    const __half* gAh = S.Ah + (size_t)mb * 128 * K;
    const __half* gAl = TWO ? (S.Al + (size_t)mb * 128 * K) : nullptr;
    const __half* gB  = S.WT + (size_t)nb * 128 * K;
    const int rows_a = min(128, S.M - mb * 128);

    auto issue = [&](int kc, int st) {
        uint32_t base = sb + st * STG;
#pragma unroll
        for (int p = 0; p < 4; p++) {
            int idx = tid + p * 256;       // 0..1023
            int row = idx >> 3, ch = idx & 7;
            bool v = row < rows_a;
            int sz = v ? 16 : 0;
            size_t go = (size_t)row * K + (size_t)kc * 64 + ch * 8;
            uint32_t d = base + (uint32_t)(row * 144 + ch * 16);
            cpa16(d, v ? (gAh + go) : gAh, sz);
            if (TWO) cpa16(d + GTILE, v ? (gAl + go) : gAl, sz);
            cpa16(d + BOFF, gB + go, 16);
        }
        cp_commit();
    };

    float c[2][8][4];
#pragma unroll
    for (int i = 0; i < 2; i++)
#pragma unroll
        for (int j = 0; j < 8; j++)
#pragma unroll
            for (int e = 0; e < 4; e++) c[i][j][e] = 0.f;

    const int nch = K / 64;
    issue(0, 0);

    const int a_r  = wm * 32 + (lane & 15);
    const int a_c8 = (lane >> 4) * 8;
    const int b_n  = wn * 64 + (lane >> 4) * 8 + (lane & 7);
    const int b_c8 = ((lane >> 3) & 1) * 8;

    for (int kc = 0; kc < nch; kc++) {
        const int st = kc & 1;
        if (kc + 1 < nch) { issue(kc + 1, st ^ 1); cp_wait<1>(); }
        else              { cp_wait<0>(); }
        __syncthreads();

        const uint32_t sa = sb + st * STG;
#pragma unroll
        for (int ks = 0; ks < 4; ks++) {
            uint32_t ah[2][4], al[2][4];
#pragma unroll
            for (int mf = 0; mf < 2; mf++) {
                uint32_t ad = sa + (uint32_t)((a_r + mf * 16) * 144 + (ks * 16 + a_c8) * 2);
                ldsm4(ah[mf], ad);
                if (TWO) ldsm4(al[mf], ad + GTILE);
            }
            uint32_t bh[8][2];
#pragma unroll
            for (int nf = 0; nf < 4; nf++) {
                uint32_t bd = sa + BOFF +
                              (uint32_t)((b_n + nf * 16) * 144 + (ks * 16 + b_c8) * 2);
                uint32_t t0[4];
                ldsm4(t0, bd);
                bh[nf * 2][0] = t0[0]; bh[nf * 2][1] = t0[1];
                bh[nf * 2 + 1][0] = t0[2]; bh[nf * 2 + 1][1] = t0[3];
            }
#pragma unroll
            for (int mf = 0; mf < 2; mf++)
#pragma unroll
                for (int nf = 0; nf < 8; nf++) {
                    mma_f16(c[mf][nf], ah[mf], bh[nf][0], bh[nf][1]);
                    if (TWO) mma_f16(c[mf][nf], al[mf], bh[nf][0], bh[nf][1]);
                }
        }
        __syncthreads();
    }

#pragma unroll
    for (int mf = 0; mf < 2; mf++) {
#pragma unroll
        for (int nf = 0; nf < 8; nf++) {
            int row0 = mb * 128 + wm * 32 + mf * 16 + (lane >> 2);
            int col  = nb * 128 + wn * 64 + nf * 8 + (lane & 3) * 2;
            float b0 = S.bias[col], b1 = S.bias[col + 1];
            if (row0 < S.M) {
                float2 o0 = make_float2(c[mf][nf][0] + b0, c[mf][nf][1] + b1);
                *(float2*)(S.out + (size_t)row0 * HID + col) = o0;
            }
            int row1 = row0 + 8;
            if (row1 < S.M) {
                float2 o1 = make_float2(c[mf][nf][2] + b0, c[mf][nf][3] + b1);
                *(float2*)(S.out + (size_t)row1 * HID + col) = o1;
            }
        }
    }
}

#define GEMM_SMEM1 (2 * 2 * GTILE)    // 73728
#define GEMM_SMEM2 (2 * 3 * GTILE)    // 110592

// ---------------- flash attention, fp16 (Q hi/lo; K,V single; P single) ----------------
#define APITCH 272
#define AQ_H   0
#define AQ_L   34816
#define AST0   69632
#define AKV_V  17408
#define ASTAGE 34816
#define ATTN_SMEM (AST0 + 2 * ASTAGE)   // 139264

__global__ __launch_bounds__(256) void attn_mma(
    const __half* __restrict__ Qh, const __half* __restrict__ Ql,
    const __half* __restrict__ Kh, const __half* __restrict__ Vh,
    __half* __restrict__ cxh)
{
    extern __shared__ char smem[];
    const uint32_t sb = smem_u32(smem);
    const int tid = threadIdx.x, w = tid >> 5, lane = tid & 31;
    const int mb = blockIdx.x, h = blockIdx.y;
    const size_t hbase = (size_t)h * S_TOT * HD;

#pragma unroll
    for (int i = 0; i < 8; i++) {
        int c = tid + i * 256;
        int row = c >> 4, ch = c & 15;
        size_t g = hbase + (size_t)(mb * 128 + row) * HD + ch * 8;
        *(uint4*)(smem + AQ_H + row * APITCH + ch * 16) = *(const uint4*)(Qh + g);
        *(uint4*)(smem + AQ_L + row * APITCH + ch * 16) = *(const uint4*)(Ql + g);
    }

    auto issueKV = [&](int t, int st) {
        uint32_t base = sb + AST0 + st * ASTAGE;
        int key0 = t * 64;
#pragma unroll
        for (int i = 0; i < 4; i++) {
            int c = tid + i * 256;
            int row = c >> 4, ch = c & 15;
            size_t g = hbase + (size_t)(key0 + row) * HD + ch * 8;
            uint32_t d = base + row * APITCH + ch * 16;
            cpa16(d,         Kh + g, 16);
            cpa16(d + AKV_V, Vh + g, 16);
        }
        cp_commit();
    };

    float co[16][4];
#pragma unroll
    for (int i = 0; i < 16; i++)
#pragma unroll
        for (int e = 0; e < 4; e++) co[i][e] = 0.f;
    float m0 = -1e30f, m1 = -1e30f, l0 = 0.f, l1 = 0.f;

    const uint32_t qa_ro = (uint32_t)((w * 16 + (lane & 15)) * APITCH + ((lane >> 4) * 8) * 2);
    const int b_n  = (lane >> 4) * 8 + (lane & 7);
    const int b_c8 = ((lane >> 3) & 1) * 8;
    const uint32_t vt_ro = (uint32_t)((lane & 15) * APITCH + ((lane >> 4) * 8) * 2);

    issueKV(0, 0);

    const int NT = S_TOT / 64;
    for (int t = 0; t < NT; t++) {
        const int st = t & 1;
        if (t + 1 < NT) { issueKV(t + 1, st ^ 1); cp_wait<1>(); }
        else            { cp_wait<0>(); }
        __syncthreads();

        const uint32_t kbase = sb + AST0 + st * ASTAGE;

        float cs[8][4];
#pragma unroll
        for (int i = 0; i < 8; i++)
#pragma unroll
            for (int e = 0; e < 4; e++) cs[i][e] = 0.f;

#pragma unroll
        for (int kt = 0; kt < 8; kt++) {
            uint32_t ah[4], al[4];
            uint32_t qa = sb + qa_ro + (uint32_t)(kt * 32);
            ldsm4(ah, qa + AQ_H);
            ldsm4(al, qa + AQ_L);
#pragma unroll
            for (int nfp = 0; nfp < 4; nfp++) {
                uint32_t bd = kbase + (uint32_t)((b_n + nfp * 16) * APITCH + (kt * 16 + b_c8) * 2);
                uint32_t t0[4];
                ldsm4(t0, bd);
                mma_f16(cs[nfp * 2],     ah, t0[0], t0[1]);
                mma_f16(cs[nfp * 2 + 1], ah, t0[2], t0[3]);
                mma_f16(cs[nfp * 2],     al, t0[0], t0[1]);
                mma_f16(cs[nfp * 2 + 1], al, t0[2], t0[3]);
            }
        }

        float mx0 = m0, mx1 = m1;
#pragma unroll
        for (int nf = 0; nf < 8; nf++) {
            mx0 = fmaxf(mx0, fmaxf(cs[nf][0], cs[nf][1]));
            mx1 = fmaxf(mx1, fmaxf(cs[nf][2], cs[nf][3]));
        }
        mx0 = fmaxf(mx0, __shfl_xor_sync(0xffffffffu, mx0, 1));
        mx0 = fmaxf(mx0, __shfl_xor_sync(0xffffffffu, mx0, 2));
        mx1 = fmaxf(mx1, __shfl_xor_sync(0xffffffffu, mx1, 1));
        mx1 = fmaxf(mx1, __shfl_xor_sync(0xffffffffu, mx1, 2));
        float corr0 = __expf(m0 - mx0), corr1 = __expf(m1 - mx1);
        m0 = mx0; m1 = mx1;

        float rs0 = 0.f, rs1 = 0.f;
        uint32_t ph[4][4];
#pragma unroll
        for (int kt = 0; kt < 4; kt++) {
#pragma unroll
            for (int hh = 0; hh < 2; hh++) {
                int nf = 2 * kt + hh;
                float p0 = __expf(cs[nf][0] - m0), p1 = __expf(cs[nf][1] - m0);
                float p2 = __expf(cs[nf][2] - m1), p3 = __expf(cs[nf][3] - m1);
                rs0 += p0 + p1; rs1 += p2 + p3;
                ph[kt][hh * 2]     = packhf(p0, p1);
                ph[kt][hh * 2 + 1] = packhf(p2, p3);
            }
        }
        rs0 += __shfl_xor_sync(0xffffffffu, rs0, 1);
        rs0 += __shfl_xor_sync(0xffffffffu, rs0, 2);
        rs1 += __shfl_xor_sync(0xffffffffu, rs1, 1);
        rs1 += __shfl_xor_sync(0xffffffffu, rs1, 2);
        l0 = l0 * corr0 + rs0;
        l1 = l1 * corr1 + rs1;

#pragma unroll
        for (int nf = 0; nf < 16; nf++) {
            co[nf][0] *= corr0; co[nf][1] *= corr0;
            co[nf][2] *= corr1; co[nf][3] *= corr1;
        }

        const uint32_t vbase = kbase + AKV_V;
#pragma unroll
        for (int kt = 0; kt < 4; kt++) {
#pragma unroll
            for (int np = 0; np < 8; np++) {
                uint32_t vd = vbase + vt_ro + (uint32_t)(kt * 16 * APITCH + np * 32);
                uint32_t th[4];
                ldsm4t(th, vd);
                mma_f16(co[np * 2],     ph[kt], th[0], th[1]);
                mma_f16(co[np * 2 + 1], ph[kt], th[2], th[3]);
            }
        }
        __syncthreads();
    }

    // epilogue: write fp16 ctx (hi only)
    float i0 = 1.f / l0, i1 = 1.f / l1;
    int r0g = mb * 128 + w * 16 + (lane >> 2);
#pragma unroll
    for (int nf = 0; nf < 16; nf++) {
        int col = h * HD + nf * 8 + (lane & 3) * 2;
        *(__half2*)(cxh + (size_t)r0g * HID + col) =
            __floats2half2_rn(co[nf][0] * i0, co[nf][1] * i0);
        *(__half2*)(cxh + (size_t)(r0g + 8) * HID + col) =
            __floats2half2_rn(co[nf][2] * i1, co[nf][3] * i1);
    }
}

// ---------------- fp32 -> fp16 (hi only) ----------------
__global__ __launch_bounds__(256) void conv_h(
    const float* __restrict__ x, __half* __restrict__ h, int n4)
{
    int i = blockIdx.x * 256 + threadIdx.x;
    if (i >= n4) return;
    float4 v = ((const float4*)x)[i];
    ((__half2*)h)[2 * i]     = __floats2half2_rn(v.x, v.y);
    ((__half2*)h)[2 * i + 1] = __floats2half2_rn(v.z, v.w);
}

// ---------------- W[K][N] fp32 -> W^T[N][K] fp16, batched by z ----------------
struct WTask { const float* W; __half* T; };

__global__ __launch_bounds__(256) void conv_wT(
    WTask t0, WTask t1, WTask t2, int K, int N)
{
    __shared__ float s[32][33];
    const WTask T = (blockIdx.z == 0) ? t0 : ((blockIdx.z == 1) ? t1 : t2);
    const int tx = threadIdx.x & 31, ty = threadIdx.x >> 5;
    const int k0 = blockIdx.y * 32, n0 = blockIdx.x * 32;
#pragma unroll
    for (int r = 0; r < 4; r++)
        s[ty + r * 8][tx] = T.W[(size_t)(k0 + ty + r * 8) * N + n0 + tx];
    __syncthreads();
#pragma unroll
    for (int r = 0; r < 4; r++) {
        int n = n0 + ty + r * 8, k = k0 + tx;
        T.T[(size_t)n * K + k] = __float2half_rn(s[tx][ty + r * 8]);
    }
}

// ---------------- prepare: rms + rope + head layout -> fp16 ----------------
__global__ __launch_bounds__(128) void prepare_qkv(
    const float* __restrict__ q,  const float* __restrict__ k,  const float* __restrict__ v,
    const float* __restrict__ eq, const float* __restrict__ ek, const float* __restrict__ ev,
    const float* __restrict__ nq, const float* __restrict__ nk,
    const float* __restrict__ naq,const float* __restrict__ nak,
    const float* __restrict__ cosr, const float* __restrict__ sinr,
    __half* __restrict__ qh, __half* __restrict__ ql,
    __half* __restrict__ kh, __half* __restrict__ vh)
{
    const int s = blockIdx.x;
    const int h = blockIdx.y;
    const int d = threadIdx.x;
    const int col = h * HD + d;

    const float *sq, *sk, *sv, *wq, *wk;
    if (s < S_TXT) {
        sq = eq + (size_t)s * HID; sk = ek + (size_t)s * HID; sv = ev + (size_t)s * HID;
        wq = naq; wk = nak;
    } else {
        int si = s - S_TXT;
        sq = q + (size_t)si * HID; sk = k + (size_t)si * HID; sv = v + (size_t)si * HID;
        wq = nq; wk = nk;
    }
    float xq = sq[col], xk = sk[col], xv = sv[col];

    __shared__ float red[8];
    float s2q = xq * xq, s2k = xk * xk;
#pragma unroll
    for (int o = 16; o; o >>= 1) {
        s2q += __shfl_xor_sync(0xffffffffu, s2q, o);
        s2k += __shfl_xor_sync(0xffffffffu, s2k, o);
    }
    int wid = d >> 5, lid = d & 31;
    if (lid == 0) { red[wid] = s2q; red[4 + wid] = s2k; }
    __syncthreads();
    float tq = red[0] + red[1] + red[2] + red[3];
    float tk = red[4] + red[5] + red[6] + red[7];
    float rq = rsqrtf(tq / (float)HD + EPS_F);
    float rk = rsqrtf(tk / (float)HD + EPS_F);
    float nxq = xq * rq * wq[d];
    float nxk = xk * rk * wk[d];

    __shared__ float shq[128], shk[128];
    shq[d] = nxq; shk[d] = nxk;
    __syncthreads();

    float c  = cosr[(size_t)s * HD + d];
    float sn = sinr[(size_t)s * HD + d];
    float oq, ok;
    if ((d & 1) == 0) {
        oq = nxq * c - shq[d + 1] * sn;
        ok = nxk * c - shk[d + 1] * sn;
    } else {
        oq = nxq * c + shq[d - 1] * sn;
        ok = nxk * c + shk[d - 1] * sn;
    }
    oq *= SM_SCALE;

    size_t o = ((size_t)h * S_TOT + s) * HD + d;
    __half hq = __float2half_rn(oq);
    qh[o] = hq;
    ql[o] = __float2half_rn(oq - __half2float(hq));
    kh[o] = __float2half_rn(ok);
    vh[o] = __float2half_rn(xv);
}

// ---------------- IP attention: RMW on fp16 ctx (hi only) ----------------
__global__ __launch_bounds__(256) void ip_attn(
    const float* __restrict__ q, const float* __restrict__ ipk, const float* __restrict__ ipv,
    const float* __restrict__ wqn, const float* __restrict__ wkn,
    __half* __restrict__ cxh)
{
    __shared__ float sK[LIP * HD];
    __shared__ float sV[LIP * HD];
    const int t = threadIdx.x, h = blockIdx.y;
    const int w = t >> 5, lane = t & 31;

#pragma unroll
    for (int i = 0; i < 8; i++) {
        int idx = t + i * 256;
        int r = idx >> 7, c = idx & 127;
        sK[idx] = ipk[(size_t)r * HID + h * HD + c];
        sV[idx] = ipv[(size_t)r * HID + h * HD + c];
    }
    __syncthreads();

    float4 wk4 = *(const float4*)(wkn + lane * 4);
    for (int rr = w; rr < LIP; rr += 8) {
        float4 kv = ((float4*)sK)[rr * 32 + lane];
        float ss = kv.x * kv.x + kv.y * kv.y + kv.z * kv.z + kv.w * kv.w;
#pragma unroll
        for (int o = 16; o; o >>= 1) ss += __shfl_xor_sync(0xffffffffu, ss, o);
        float r = rsqrtf(ss / (float)HD + EPS_F);
        kv.x *= r * wk4.x; kv.y *= r * wk4.y; kv.z *= r * wk4.z; kv.w *= r * wk4.w;
        ((float4*)sK)[rr * 32 + lane] = kv;
    }
    __syncthreads();

    const int s = blockIdx.x * 8 + w;
    float4 q4 = *(const float4*)(q + (size_t)s * HID + h * HD + lane * 4);
    float ss = q4.x * q4.x + q4.y * q4.y + q4.z * q4.z + q4.w * q4.w;
#pragma unroll
    for (int o = 16; o; o >>= 1) ss += __shfl_xor_sync(0xffffffffu, ss, o);
    float rq = rsqrtf(ss / (float)HD + EPS_F);
    float4 wq4 = *(const float4*)(wqn + lane * 4);
    q4.x *= rq * wq4.x; q4.y *= rq * wq4.y; q4.z *= rq * wq4.z; q4.w *= rq * wq4.w;

    float sc[LIP];
#pragma unroll
    for (int j = 0; j < LIP; j++) {
        float4 kv = ((const float4*)sK)[j * 32 + lane];
        float d = q4.x * kv.x + q4.y * kv.y + q4.z * kv.z + q4.w * kv.w;
#pragma unroll
        for (int o = 16; o; o >>= 1) d += __shfl_xor_sync(0xffffffffu, d, o);
        sc[j] = d * SM_SCALE;
    }
    float mx = sc[0];
#pragma unroll
    for (int j = 1; j < LIP; j++) mx = fmaxf(mx, sc[j]);
    float l = 0.f;
#pragma unroll
    for (int j = 0; j < LIP; j++) { sc[j] = __expf(sc[j] - mx); l += sc[j]; }
    float inv = 1.f / l;

    float4 acc = make_float4(0.f, 0.f, 0.f, 0.f);
#pragma unroll
    for (int j = 0; j < LIP; j++) {
        float p = sc[j] * inv;
        float4 vv = ((const float4*)sV)[j * 32 + lane];
        acc.x += p * vv.x; acc.y += p * vv.y; acc.z += p * vv.z; acc.w += p * vv.w;
    }

    size_t o = (size_t)(S_TXT + s) * HID + h * HD + lane * 4;
    __half2 h01 = *(__half2*)(cxh + o), h23 = *(__half2*)(cxh + o + 2);
    *(__half2*)(cxh + o) =
        __floats2half2_rn(__half2float(h01.x) + acc.x, __half2float(h01.y) + acc.y);
    *(__half2*)(cxh + o + 2) =
        __floats2half2_rn(__half2float(h23.x) + acc.z, __half2float(h23.y) + acc.w);
}

// ---------------- host launch ----------------
static float* symf(const void* s) { void* p = nullptr; cudaGetSymbolAddress(&p, s); return (float*)p; }
static __half* symh(const void* s) { void* p = nullptr; cudaGetSymbolAddress(&p, s); return (__half*)p; }

extern "C" void kernel_launch(void* const* d_in, const int* in_sizes, int n_in,
                              void* d_out, int out_size)
{
    const float* hs    = (const float*)d_in[0];
    const float* enc   = (const float*)d_in[1];
    const float* iph   = (const float*)d_in[2];
    const float* rcos  = (const float*)d_in[3];
    const float* rsin  = (const float*)d_in[4];
    const float* Wq    = (const float*)d_in[5];
    const float* bq    = (const float*)d_in[6];
    const float* Wk    = (const float*)d_in[7];
    const float* bk    = (const float*)d_in[8];
    const float* Wv    = (const float*)d_in[9];
    const float* bv    = (const float*)d_in[10];
    const float* nqw   = (const float*)d_in[11];
    const float* nkw   = (const float*)d_in[12];
    const float* Waq   = (const float*)d_in[13];
    const float* baq   = (const float*)d_in[14];
    const float* Wak   = (const float*)d_in[15];
    const float* bak   = (const float*)d_in[16];
    const float* Wav   = (const float*)d_in[17];
    const float* bav   = (const float*)d_in[18];
    const float* naqw  = (const float*)d_in[19];
    const float* nakw  = (const float*)d_in[20];
    const float* Wo    = (const float*)d_in[21];
    const float* bo    = (const float*)d_in[22];
    const float* Wadd  = (const float*)d_in[23];
    const float* badd  = (const float*)d_in[24];
    const float* Wkip  = (const float*)d_in[25];
    const float* bkip  = (const float*)d_in[26];
    const float* Wvip  = (const float*)d_in[27];
    const float* bvip  = (const float*)d_in[28];
    const float* nipq  = (const float*)d_in[29];
    const float* nipk  = (const float*)d_in[30];

    float* out = (float*)d_out;

    float* pq   = symf(g_q);   float* pk   = symf(g_k);   float* pv   = symf(g_v);
    float* peq  = symf(g_eq);  float* pek  = symf(g_ek);  float* pev  = symf(g_ev);
    float* pipk = symf(g_ipk); float* pipv = symf(g_ipv);

    __half *aqh = symh(g_aqh), *aql = symh(g_aql);
    __half *akh = symh(g_akh), *avh = symh(g_avh);

    __half *hsh = symh(g_hs_h);
    __half *ech = symh(g_enc_h);
    __half *iph_h = symh(g_iph_h);
    __half *cxh = symh(g_ctxh), *cxl = symh(g_ctxl);
    __half *wqT = symh(g_WqT),  *wkT = symh(g_WkT),  *wvT = symh(g_WvT);
    __half *waqT = symh(g_WaqT), *wakT = symh(g_WakT), *wavT = symh(g_WavT);
    __half *woT = symh(g_WoT),  *wadT = symh(g_WadT);
    __half *wkiT = symh(g_WkiT), *wviT = symh(g_WviT);

    cudaFuncSetAttribute(gemm_mma<false>, cudaFuncAttributeMaxDynamicSharedMemorySize, GEMM_SMEM1);
    cudaFuncSetAttribute(gemm_mma<true>,  cudaFuncAttributeMaxDynamicSharedMemorySize, GEMM_SMEM2);
    cudaFuncSetAttribute(attn_mma, cudaFuncAttributeMaxDynamicSharedMemorySize, ATTN_SMEM);

    dim3 wg(HID / 32, HID / 32, 3);
    dim3 wg2(HID / 32, HID / 32, 2);
    dim3 wgip(HID / 32, IPD / 32, 2);

    // L0, L1, L2
    conv_wT<<<wg, 256>>>(WTask{Wq, wqT}, WTask{Wk, wkT}, WTask{Wv, wvT}, HID, HID);
    conv_h<<<(S_IMG * HID / 4 + 255) / 256, 256>>>(hs, hsh, S_IMG * HID / 4);
    conv_wT<<<wg, 256>>>(WTask{Waq, waqT}, WTask{Wak, wakT}, WTask{Wav, wavT}, HID, HID);

    // L3: big img q/k/v GEMM, 1-term (ncu capture slot)
    GemmSet sq{hsh, nullptr, wqT, bq, pq, S_IMG, HID};
    GemmSet sk{hsh, nullptr, wkT, bk, pk, S_IMG, HID};
    GemmSet sv{hsh, nullptr, wvT, bv, pv, S_IMG, HID};
    gemm_mma<false><<<dim3(HID / 128, S_IMG / 128, 3), 256, GEMM_SMEM1>>>(sq, sk, sv);

    // L4..L6
    conv_h<<<(S_TXT * HID / 4 + 255) / 256, 256>>>(enc, ech, S_TXT * HID / 4);
    conv_h<<<(LIP * IPD / 4 + 255) / 256, 256>>>(iph, iph_h, LIP * IPD / 4);
    conv_wT<<<wgip, 256>>>(WTask{Wkip, wkiT}, WTask{Wvip, wviT}, WTask{Wkip, wkiT}, IPD, HID);

    // L7: enc q/k/v GEMM, 1-term
    GemmSet se1{ech, nullptr, waqT, baq, peq, S_TXT, HID};
    GemmSet se2{ech, nullptr, wakT, bak, pek, S_TXT, HID};
    GemmSet se3{ech, nullptr, wavT, bav, pev, S_TXT, HID};
    gemm_mma<false><<<dim3(HID / 128, S_TXT / 128, 3), 256, GEMM_SMEM1>>>(se1, se2, se3);

    // L8: ip k/v GEMM, 1-term
    GemmSet si1{iph_h, nullptr, wkiT, bkip, pipk, LIP, IPD};
    GemmSet si2{iph_h, nullptr, wviT, bvip, pipv, LIP, IPD};
    gemm_mma<false><<<dim3(HID / 128, 1, 2), 256, GEMM_SMEM1>>>(si1, si2, si1);

    // L9: output-projection weights
    conv_wT<<<wg2, 256>>>(WTask{Wo, woT}, WTask{Wadd, wadT}, WTask{Wo, woT}, HID, HID);

    // L10: rms + rope + head layout
    prepare_qkv<<<dim3(S_TOT, NH), 128>>>(pq, pk, pv, peq, pek, pev,
                                          nqw, nkw, naqw, nakw, rcos, rsin,
                                          aqh, aql, akh, avh);

    // L11, L12: attention (writes fp16 ctx hi), IP attention (RMW)
    attn_mma<<<dim3(S_TOT / 128, NH), 256, ATTN_SMEM>>>(aqh, aql, akh, avh, cxh);
    ip_attn<<<dim3(S_IMG / 8, NH), 256>>>(pq, pipk, pipv, nipq, nipk, cxh);

    // L13: merged output GEMMs, 1-term ctx (z=0: img via Wo, z=1: enc via Wadd)
    GemmSet so{cxh, nullptr, woT, bo, out, S_IMG, HID};
    so.Ah = cxh + (size_t)S_TXT * HID;
    GemmSet sa{cxh, nullptr, wadT, badd, out + (size_t)S_IMG * HID, S_TXT, HID};
    gemm_mma<false><<<dim3(HID / 128, S_IMG / 128, 2), 256, GEMM_SMEM1>>>(so, sa, so);

    // keep gemm_mma<true> referenced (unused this round; cxl retained for it)
    if (out_size < 0) {
        GemmSet dummy{cxh, cxl, woT, bo, out, 0, HID};
        gemm_mma<true><<<dim3(1, 1, 1), 256, GEMM_SMEM2>>>(dummy, dummy, dummy);
    }
}

// round 15
// speedup vs baseline: 1.5112x; 1.0191x over previous
#include <cuda_runtime.h>
#include <cuda_fp16.h>
#include <cstdint>

// ---------------- problem constants ----------------
#define S_IMG 1024
#define S_TXT 512
#define S_TOT 1536
#define NH    24
#define HD    128
#define HID   3072
#define IPD   2048
#define LIP   16
#define EPS_F 1e-6f
#define SM_SCALE 0.08838834764831845f  // 1/sqrt(128)

// ---------------- fp32 scratch ----------------
__device__ float g_q [S_IMG * HID];
__device__ float g_k [S_IMG * HID];
__device__ float g_v [S_IMG * HID];
__device__ float g_eq[S_TXT * HID];
__device__ float g_ek[S_TXT * HID];
__device__ float g_ev[S_TXT * HID];
__device__ float g_ipk[LIP * HID];
__device__ float g_ipv[LIP * HID];

// fp16 q (hi/lo, pre-scaled) + k/v (single) in [H][S][D] — attention path
__device__ __align__(16) __half g_aqh[(size_t)NH * S_TOT * HD], g_aql[(size_t)NH * S_TOT * HD];
__device__ __align__(16) __half g_akh[(size_t)NH * S_TOT * HD];
__device__ __align__(16) __half g_avh[(size_t)NH * S_TOT * HD];

// ---------------- fp16 activations (hi only) ----------------
__device__ __align__(16) __half g_hs_h [S_IMG * HID];
__device__ __align__(16) __half g_enc_h[S_TXT * HID];
__device__ __align__(16) __half g_iph_h[LIP * IPD];
__device__ __align__(16) __half g_ctxh [S_TOT * HID];
// transposed weights [N][K] fp16
__device__ __align__(16) __half g_WqT [HID * HID];
__device__ __align__(16) __half g_WkT [HID * HID];
__device__ __align__(16) __half g_WvT [HID * HID];
__device__ __align__(16) __half g_WaqT[HID * HID];
__device__ __align__(16) __half g_WakT[HID * HID];
__device__ __align__(16) __half g_WavT[HID * HID];
__device__ __align__(16) __half g_WoT [HID * HID];
__device__ __align__(16) __half g_WadT[HID * HID];
__device__ __align__(16) __half g_WkiT[HID * IPD];
__device__ __align__(16) __half g_WviT[HID * IPD];

// ---------------- low-level helpers ----------------
__device__ __forceinline__ uint32_t smem_u32(const void* p) {
    return (uint32_t)__cvta_generic_to_shared(p);
}
__device__ __forceinline__ void cpa16(uint32_t dst, const void* src, int sz) {
    asm volatile("cp.async.cg.shared.global [%0], [%1], 16, %2;"
                 :: "r"(dst), "l"(src), "r"(sz) : "memory");
}
__device__ __forceinline__ void cp_commit() {
    asm volatile("cp.async.commit_group;" ::: "memory");
}
template<int N> __device__ __forceinline__ void cp_wait() {
    asm volatile("cp.async.wait_group %0;" :: "n"(N) : "memory");
}
__device__ __forceinline__ void ldsm4(uint32_t* r, uint32_t addr) {
    asm volatile("ldmatrix.sync.aligned.m8n8.x4.shared.b16 {%0,%1,%2,%3}, [%4];"
                 : "=r"(r[0]), "=r"(r[1]), "=r"(r[2]), "=r"(r[3]) : "r"(addr));
}
__device__ __forceinline__ void ldsm4t(uint32_t* r, uint32_t addr) {
    asm volatile("ldmatrix.sync.aligned.m8n8.x4.trans.shared.b16 {%0,%1,%2,%3}, [%4];"
                 : "=r"(r[0]), "=r"(r[1]), "=r"(r[2]), "=r"(r[3]) : "r"(addr));
}
__device__ __forceinline__ void mma_f16(float* c, const uint32_t* a, uint32_t b0, uint32_t b1) {
    asm volatile(
        "mma.sync.aligned.m16n8k16.row.col.f32.f16.f16.f32 "
        "{%0,%1,%2,%3}, {%4,%5,%6,%7}, {%8,%9}, {%0,%1,%2,%3};"
        : "+f"(c[0]), "+f"(c[1]), "+f"(c[2]), "+f"(c[3])
        : "r"(a[0]), "r"(a[1]), "r"(a[2]), "r"(a[3]), "r"(b0), "r"(b1));
}
__device__ __forceinline__ uint32_t packhf(float a, float b) {
    __half2 t = __floats2half2_rn(a, b);
    return *(uint32_t*)&t;
}

// ---------------- GEMM: C = A @ WT^T + bias (1-term fp16 A), 3-stage ring ----------------
struct GemmSet {
    const __half* Ah;                      // [M][K]
    const __half* WT;                      // [HID][K]  (pre-transposed)
    const float*  bias; float* out;        // out [M][HID]
    int M; int K;
};

#define GTILE 18432                   // 128 rows * 144B (72 halfs, 64 used)
#define GSTAGE (2 * GTILE)            // A + B
#define GEMM_SMEM (3 * GSTAGE)        // 110592, 3 stages

__global__ __launch_bounds__(256) void gemm_mma(GemmSet s0, GemmSet s1, GemmSet s2)
{
    extern __shared__ char smem[];
    const uint32_t sb = smem_u32(smem);
    const int tid = threadIdx.x, warp = tid >> 5, lane = tid & 31;
    const GemmSet S = (blockIdx.z == 0) ? s0 : ((blockIdx.z == 1) ? s1 : s2);
    const int nb = blockIdx.x, mb = blockIdx.y;
    if (mb * 128 >= S.M) return;
    const int wm = warp & 3, wn = warp >> 2;
    const int K = S.K;

    const __half* gAh = S.Ah + (size_t)mb * 128 * K;
    const __half* gB  = S.WT + (size_t)nb * 128 * K;
    const int rows_a = min(128, S.M - mb * 128);

    auto issue = [&](int kc, int st) {
        uint32_t base = sb + st * GSTAGE;
#pragma unroll
        for (int p = 0; p < 4; p++) {
            int idx = tid + p * 256;       // 0..1023
            int row = idx >> 3, ch = idx & 7;
            bool v = row < rows_a;
            int sz = v ? 16 : 0;
            size_t go = (size_t)row * K + (size_t)kc * 64 + ch * 8;
            uint32_t d = base + (uint32_t)(row * 144 + ch * 16);
            cpa16(d,         v ? (gAh + go) : gAh, sz);
            cpa16(d + GTILE, gB + go, 16);
        }
        cp_commit();
    };

    float c[2][8][4];
#pragma unroll
    for (int i = 0; i < 2; i++)
#pragma unroll
        for (int j = 0; j < 8; j++)
#pragma unroll
            for (int e = 0; e < 4; e++) c[i][j][e] = 0.f;

    const int nch = K / 64;
    issue(0, 0);
    if (nch > 1) issue(1, 1);

    const int a_r  = wm * 32 + (lane & 15);
    const int a_c8 = (lane >> 4) * 8;
    const int b_n  = wn * 64 + (lane >> 4) * 8 + (lane & 7);
    const int b_c8 = ((lane >> 3) & 1) * 8;

    int st = 0;
    for (int kc = 0; kc < nch; kc++) {
        if (kc + 1 < nch) cp_wait<1>(); else cp_wait<0>();
        __syncthreads();   // group kc visible to all; all finished compute kc-1
        if (kc + 2 < nch) {
            int st2 = st + 2; if (st2 >= 3) st2 -= 3;
            issue(kc + 2, st2);
        }

        const uint32_t sa = sb + st * GSTAGE;
#pragma unroll
        for (int ks = 0; ks < 4; ks++) {
            uint32_t ah[2][4];
#pragma unroll
            for (int mf = 0; mf < 2; mf++) {
                uint32_t ad = sa + (uint32_t)((a_r + mf * 16) * 144 + (ks * 16 + a_c8) * 2);
                ldsm4(ah[mf], ad);
            }
            uint32_t bh[8][2];
#pragma unroll
            for (int nf = 0; nf < 4; nf++) {
                uint32_t bd = sa + GTILE +
                              (uint32_t)((b_n + nf * 16) * 144 + (ks * 16 + b_c8) * 2);
                uint32_t t0[4];
                ldsm4(t0, bd);
                bh[nf * 2][0] = t0[0]; bh[nf * 2][1] = t0[1];
                bh[nf * 2 + 1][0] = t0[2]; bh[nf * 2 + 1][1] = t0[3];
            }
#pragma unroll
            for (int mf = 0; mf < 2; mf++)
#pragma unroll
                for (int nf = 0; nf < 8; nf++)
                    mma_f16(c[mf][nf], ah[mf], bh[nf][0], bh[nf][1]);
        }
        if (++st == 3) st = 0;
    }

#pragma unroll
    for (int mf = 0; mf < 2; mf++) {
#pragma unroll
        for (int nf = 0; nf < 8; nf++) {
            int row0 = mb * 128 + wm * 32 + mf * 16 + (lane >> 2);
            int col  = nb * 128 + wn * 64 + nf * 8 + (lane & 3) * 2;
            float b0 = S.bias[col], b1 = S.bias[col + 1];
            if (row0 < S.M) {
                float2 o0 = make_float2(c[mf][nf][0] + b0, c[mf][nf][1] + b1);
                *(float2*)(S.out + (size_t)row0 * HID + col) = o0;
            }
            int row1 = row0 + 8;
            if (row1 < S.M) {
                float2 o1 = make_float2(c[mf][nf][2] + b0, c[mf][nf][3] + b1);
                *(float2*)(S.out + (size_t)row1 * HID + col) = o1;
            }
        }
    }
}

// ---------------- flash attention, fp16 (Q hi/lo; K,V single; P single), 3-stage KV ----------------
#define APITCH 272
#define AQ_H   0
#define AQ_L   34816
#define AST0   69632
#define AKV_V  17408
#define ASTAGE 34816
#define ATTN_SMEM (AST0 + 3 * ASTAGE)   // 174080

__global__ __launch_bounds__(256) void attn_mma(
    const __half* __restrict__ Qh, const __half* __restrict__ Ql,
    const __half* __restrict__ Kh, const __half* __restrict__ Vh,
    __half* __restrict__ cxh)
{
    extern __shared__ char smem[];
    const uint32_t sb = smem_u32(smem);
    const int tid = threadIdx.x, w = tid >> 5, lane = tid & 31;
    const int mb = blockIdx.x, h = blockIdx.y;
    const size_t hbase = (size_t)h * S_TOT * HD;

#pragma unroll
    for (int i = 0; i < 8; i++) {
        int c = tid + i * 256;
        int row = c >> 4, ch = c & 15;
        size_t g = hbase + (size_t)(mb * 128 + row) * HD + ch * 8;
        *(uint4*)(smem + AQ_H + row * APITCH + ch * 16) = *(const uint4*)(Qh + g);
        *(uint4*)(smem + AQ_L + row * APITCH + ch * 16) = *(const uint4*)(Ql + g);
    }

    auto issueKV = [&](int t, int st) {
        uint32_t base = sb + AST0 + st * ASTAGE;
        int key0 = t * 64;
#pragma unroll
        for (int i = 0; i < 4; i++) {
            int c = tid + i * 256;
            int row = c >> 4, ch = c & 15;
            size_t g = hbase + (size_t)(key0 + row) * HD + ch * 8;
            uint32_t d = base + row * APITCH + ch * 16;
            cpa16(d,         Kh + g, 16);
            cpa16(d + AKV_V, Vh + g, 16);
        }
        cp_commit();
    };

    float co[16][4];
#pragma unroll
    for (int i = 0; i < 16; i++)
#pragma unroll
        for (int e = 0; e < 4; e++) co[i][e] = 0.f;
    float m0 = -1e30f, m1 = -1e30f, l0 = 0.f, l1 = 0.f;

    const uint32_t qa_ro = (uint32_t)((w * 16 + (lane & 15)) * APITCH + ((lane >> 4) * 8) * 2);
    const int b_n  = (lane >> 4) * 8 + (lane & 7);
    const int b_c8 = ((lane >> 3) & 1) * 8;
    const uint32_t vt_ro = (uint32_t)((lane & 15) * APITCH + ((lane >> 4) * 8) * 2);

    const int NT = S_TOT / 64;
    issueKV(0, 0);
    issueKV(1, 1);

    int st = 0;
    for (int t = 0; t < NT; t++) {
        if (t + 1 < NT) cp_wait<1>(); else cp_wait<0>();
        __syncthreads();
        if (t + 2 < NT) {
            int st2 = st + 2; if (st2 >= 3) st2 -= 3;
            issueKV(t + 2, st2);
        }

        const uint32_t kbase = sb + AST0 + st * ASTAGE;

        float cs[8][4];
#pragma unroll
        for (int i = 0; i < 8; i++)
#pragma unroll
            for (int e = 0; e < 4; e++) cs[i][e] = 0.f;

#pragma unroll
        for (int kt = 0; kt < 8; kt++) {
            uint32_t ah[4], al[4];
            uint32_t qa = sb + qa_ro + (uint32_t)(kt * 32);
            ldsm4(ah, qa + AQ_H);
            ldsm4(al, qa + AQ_L);
#pragma unroll
            for (int nfp = 0; nfp < 4; nfp++) {
                uint32_t bd = kbase + (uint32_t)((b_n + nfp * 16) * APITCH + (kt * 16 + b_c8) * 2);
                uint32_t t0[4];
                ldsm4(t0, bd);
                mma_f16(cs[nfp * 2],     ah, t0[0], t0[1]);
                mma_f16(cs[nfp * 2 + 1], ah, t0[2], t0[3]);
                mma_f16(cs[nfp * 2],     al, t0[0], t0[1]);
                mma_f16(cs[nfp * 2 + 1], al, t0[2], t0[3]);
            }
        }

        float mx0 = m0, mx1 = m1;
#pragma unroll
        for (int nf = 0; nf < 8; nf++) {
            mx0 = fmaxf(mx0, fmaxf(cs[nf][0], cs[nf][1]));
            mx1 = fmaxf(mx1, fmaxf(cs[nf][2], cs[nf][3]));
        }
        mx0 = fmaxf(mx0, __shfl_xor_sync(0xffffffffu, mx0, 1));
        mx0 = fmaxf(mx0, __shfl_xor_sync(0xffffffffu, mx0, 2));
        mx1 = fmaxf(mx1, __shfl_xor_sync(0xffffffffu, mx1, 1));
        mx1 = fmaxf(mx1, __shfl_xor_sync(0xffffffffu, mx1, 2));
        float corr0 = __expf(m0 - mx0), corr1 = __expf(m1 - mx1);
        m0 = mx0; m1 = mx1;

        float rs0 = 0.f, rs1 = 0.f;
        uint32_t ph[4][4];
#pragma unroll
        for (int kt = 0; kt < 4; kt++) {
#pragma unroll
            for (int hh = 0; hh < 2; hh++) {
                int nf = 2 * kt + hh;
                float p0 = __expf(cs[nf][0] - m0), p1 = __expf(cs[nf][1] - m0);
                float p2 = __expf(cs[nf][2] - m1), p3 = __expf(cs[nf][3] - m1);
                rs0 += p0 + p1; rs1 += p2 + p3;
                ph[kt][hh * 2]     = packhf(p0, p1);
                ph[kt][hh * 2 + 1] = packhf(p2, p3);
            }
        }
        rs0 += __shfl_xor_sync(0xffffffffu, rs0, 1);
        rs0 += __shfl_xor_sync(0xffffffffu, rs0, 2);
        rs1 += __shfl_xor_sync(0xffffffffu, rs1, 1);
        rs1 += __shfl_xor_sync(0xffffffffu, rs1, 2);
        l0 = l0 * corr0 + rs0;
        l1 = l1 * corr1 + rs1;

#pragma unroll
        for (int nf = 0; nf < 16; nf++) {
            co[nf][0] *= corr0; co[nf][1] *= corr0;
            co[nf][2] *= corr1; co[nf][3] *= corr1;
        }

        const uint32_t vbase = kbase + AKV_V;
#pragma unroll
        for (int kt = 0; kt < 4; kt++) {
#pragma unroll
            for (int np = 0; np < 8; np++) {
                uint32_t vd = vbase + vt_ro + (uint32_t)(kt * 16 * APITCH + np * 32);
                uint32_t th[4];
                ldsm4t(th, vd);
                mma_f16(co[np * 2],     ph[kt], th[0], th[1]);
                mma_f16(co[np * 2 + 1], ph[kt], th[2], th[3]);
            }
        }
        if (++st == 3) st = 0;
    }

    // epilogue: write fp16 ctx (hi only)
    float i0 = 1.f / l0, i1 = 1.f / l1;
    int r0g = mb * 128 + w * 16 + (lane >> 2);
#pragma unroll
    for (int nf = 0; nf < 16; nf++) {
        int col = h * HD + nf * 8 + (lane & 3) * 2;
        *(__half2*)(cxh + (size_t)r0g * HID + col) =
            __floats2half2_rn(co[nf][0] * i0, co[nf][1] * i0);
        *(__half2*)(cxh + (size_t)(r0g + 8) * HID + col) =
            __floats2half2_rn(co[nf][2] * i1, co[nf][3] * i1);
    }
}

// ---------------- fp32 -> fp16 (hi only) ----------------
__global__ __launch_bounds__(256) void conv_h(
    const float* __restrict__ x, __half* __restrict__ h, int n4)
{
    int i = blockIdx.x * 256 + threadIdx.x;
    if (i >= n4) return;
    float4 v = ((const float4*)x)[i];
    ((__half2*)h)[2 * i]     = __floats2half2_rn(v.x, v.y);
    ((__half2*)h)[2 * i + 1] = __floats2half2_rn(v.z, v.w);
}

// ---------------- W[K][N] fp32 -> W^T[N][K] fp16, coalesced half2 stores ----------------
struct WTask { const float* W; __half* T; };

__global__ __launch_bounds__(256) void conv_wT(
    WTask t0, WTask t1, WTask t2, int K, int N)
{
    __shared__ float s[32][33];
    const WTask T = (blockIdx.z == 0) ? t0 : ((blockIdx.z == 1) ? t1 : t2);
    const int tx = threadIdx.x & 31, ty = threadIdx.x >> 5;
    const int k0 = blockIdx.y * 32, n0 = blockIdx.x * 32;
#pragma unroll
    for (int r = 0; r < 4; r++)
        s[ty + r * 8][tx] = T.W[(size_t)(k0 + ty + r * 8) * N + n0 + tx];
    __syncthreads();
    // store: thread handles two consecutive k for one n -> 4B stores, 128B/warp
#pragma unroll
    for (int it = 0; it < 2; it++) {
        int row = (threadIdx.x >> 4) + it * 16;   // n within tile
        int p   = threadIdx.x & 15;               // k pair index
        __half2 v = __floats2half2_rn(s[2 * p][row], s[2 * p + 1][row]);
        *(__half2*)(T.T + (size_t)(n0 + row) * K + k0 + 2 * p) = v;
    }
}

// ---------------- prepare: rms + rope + head layout -> fp16 ----------------
__global__ __launch_bounds__(128) void prepare_qkv(
    const float* __restrict__ q,  const float* __restrict__ k,  const float* __restrict__ v,
    const float* __restrict__ eq, const float* __restrict__ ek, const float* __restrict__ ev,
    const float* __restrict__ nq, const float* __restrict__ nk,
    const float* __restrict__ naq,const float* __restrict__ nak,
    const float* __restrict__ cosr, const float* __restrict__ sinr,
    __half* __restrict__ qh, __half* __restrict__ ql,
    __half* __restrict__ kh, __half* __restrict__ vh)
{
    const int s = blockIdx.x;
    const int h = blockIdx.y;
    const int d = threadIdx.x;
    const int col = h * HD + d;

    const float *sq, *sk, *sv, *wq, *wk;
    if (s < S_TXT) {
        sq = eq + (size_t)s * HID; sk = ek + (size_t)s * HID; sv = ev + (size_t)s * HID;
        wq = naq; wk = nak;
    } else {
        int si = s - S_TXT;
        sq = q + (size_t)si * HID; sk = k + (size_t)si * HID; sv = v + (size_t)si * HID;
        wq = nq; wk = nk;
    }
    float xq = sq[col], xk = sk[col], xv = sv[col];

    __shared__ float red[8];
    float s2q = xq * xq, s2k = xk * xk;
#pragma unroll
    for (int o = 16; o; o >>= 1) {
        s2q += __shfl_xor_sync(0xffffffffu, s2q, o);
        s2k += __shfl_xor_sync(0xffffffffu, s2k, o);
    }
    int wid = d >> 5, lid = d & 31;
    if (lid == 0) { red[wid] = s2q; red[4 + wid] = s2k; }
    __syncthreads();
    float tq = red[0] + red[1] + red[2] + red[3];
    float tk = red[4] + red[5] + red[6] + red[7];
    float rq = rsqrtf(tq / (float)HD + EPS_F);
    float rk = rsqrtf(tk / (float)HD + EPS_F);
    float nxq = xq * rq * wq[d];
    float nxk = xk * rk * wk[d];

    __shared__ float shq[128], shk[128];
    shq[d] = nxq; shk[d] = nxk;
    __syncthreads();

    float c  = cosr[(size_t)s * HD + d];
    float sn = sinr[(size_t)s * HD + d];
    float oq, ok;
    if ((d & 1) == 0) {
        oq = nxq * c - shq[d + 1] * sn;
        ok = nxk * c - shk[d + 1] * sn;
    } else {
        oq = nxq * c + shq[d - 1] * sn;
        ok = nxk * c + shk[d - 1] * sn;
    }
    oq *= SM_SCALE;

    size_t o = ((size_t)h * S_TOT + s) * HD + d;
    __half hq = __float2half_rn(oq);
    qh[o] = hq;
    ql[o] = __float2half_rn(oq - __half2float(hq));
    kh[o] = __float2half_rn(ok);
    vh[o] = __float2half_rn(xv);
}

// ---------------- IP attention: RMW on fp16 ctx (hi only) ----------------
__global__ __launch_bounds__(256) void ip_attn(
    const float* __restrict__ q, const float* __restrict__ ipk, const float* __restrict__ ipv,
    const float* __restrict__ wqn, const float* __restrict__ wkn,
    __half* __restrict__ cxh)
{
    __shared__ float sK[LIP * HD];
    __shared__ float sV[LIP * HD];
    const int t = threadIdx.x, h = blockIdx.y;
    const int w = t >> 5, lane = t & 31;

#pragma unroll
    for (int i = 0; i < 8; i++) {
        int idx = t + i * 256;
        int r = idx >> 7, c = idx & 127;
        sK[idx] = ipk[(size_t)r * HID + h * HD + c];
        sV[idx] = ipv[(size_t)r * HID + h * HD + c];
    }
    __syncthreads();

    float4 wk4 = *(const float4*)(wkn + lane * 4);
    for (int rr = w; rr < LIP; rr += 8) {
        float4 kv = ((float4*)sK)[rr * 32 + lane];
        float ss = kv.x * kv.x + kv.y * kv.y + kv.z * kv.z + kv.w * kv.w;
#pragma unroll
        for (int o = 16; o; o >>= 1) ss += __shfl_xor_sync(0xffffffffu, ss, o);
        float r = rsqrtf(ss / (float)HD + EPS_F);
        kv.x *= r * wk4.x; kv.y *= r * wk4.y; kv.z *= r * wk4.z; kv.w *= r * wk4.w;
        ((float4*)sK)[rr * 32 + lane] = kv;
    }
    __syncthreads();

    const int s = blockIdx.x * 8 + w;
    float4 q4 = *(const float4*)(q + (size_t)s * HID + h * HD + lane * 4);
    float ss = q4.x * q4.x + q4.y * q4.y + q4.z * q4.z + q4.w * q4.w;
#pragma unroll
    for (int o = 16; o; o >>= 1) ss += __shfl_xor_sync(0xffffffffu, ss, o);
    float rq = rsqrtf(ss / (float)HD + EPS_F);
    float4 wq4 = *(const float4*)(wqn + lane * 4);
    q4.x *= rq * wq4.x; q4.y *= rq * wq4.y; q4.z *= rq * wq4.z; q4.w *= rq * wq4.w;

    float sc[LIP];
#pragma unroll
    for (int j = 0; j < LIP; j++) {
        float4 kv = ((const float4*)sK)[j * 32 + lane];
        float d = q4.x * kv.x + q4.y * kv.y + q4.z * kv.z + q4.w * kv.w;
#pragma unroll
        for (int o = 16; o; o >>= 1) d += __shfl_xor_sync(0xffffffffu, d, o);
        sc[j] = d * SM_SCALE;
    }
    float mx = sc[0];
#pragma unroll
    for (int j = 1; j < LIP; j++) mx = fmaxf(mx, sc[j]);
    float l = 0.f;
#pragma unroll
    for (int j = 0; j < LIP; j++) { sc[j] = __expf(sc[j] - mx); l += sc[j]; }
    float inv = 1.f / l;

    float4 acc = make_float4(0.f, 0.f, 0.f, 0.f);
#pragma unroll
    for (int j = 0; j < LIP; j++) {
        float p = sc[j] * inv;
        float4 vv = ((const float4*)sV)[j * 32 + lane];
        acc.x += p * vv.x; acc.y += p * vv.y; acc.z += p * vv.z; acc.w += p * vv.w;
    }

    size_t o = (size_t)(S_TXT + s) * HID + h * HD + lane * 4;
    __half2 h01 = *(__half2*)(cxh + o), h23 = *(__half2*)(cxh + o + 2);
    *(__half2*)(cxh + o) =
        __floats2half2_rn(__half2float(h01.x) + acc.x, __half2float(h01.y) + acc.y);
    *(__half2*)(cxh + o + 2) =
        __floats2half2_rn(__half2float(h23.x) + acc.z, __half2float(h23.y) + acc.w);
}

// ---------------- host launch ----------------
static float* symf(const void* s) { void* p = nullptr; cudaGetSymbolAddress(&p, s); return (float*)p; }
static __half* symh(const void* s) { void* p = nullptr; cudaGetSymbolAddress(&p, s); return (__half*)p; }

extern "C" void kernel_launch(void* const* d_in, const int* in_sizes, int n_in,
                              void* d_out, int out_size)
{
    const float* hs    = (const float*)d_in[0];
    const float* enc   = (const float*)d_in[1];
    const float* iph   = (const float*)d_in[2];
    const float* rcos  = (const float*)d_in[3];
    const float* rsin  = (const float*)d_in[4];
    const float* Wq    = (const float*)d_in[5];
    const float* bq    = (const float*)d_in[6];
    const float* Wk    = (const float*)d_in[7];
    const float* bk    = (const float*)d_in[8];
    const float* Wv    = (const float*)d_in[9];
    const float* bv    = (const float*)d_in[10];
    const float* nqw   = (const float*)d_in[11];
    const float* nkw   = (const float*)d_in[12];
    const float* Waq   = (const float*)d_in[13];
    const float* baq   = (const float*)d_in[14];
    const float* Wak   = (const float*)d_in[15];
    const float* bak   = (const float*)d_in[16];
    const float* Wav   = (const float*)d_in[17];
    const float* bav   = (const float*)d_in[18];
    const float* naqw  = (const float*)d_in[19];
    const float* nakw  = (const float*)d_in[20];
    const float* Wo    = (const float*)d_in[21];
    const float* bo    = (const float*)d_in[22];
    const float* Wadd  = (const float*)d_in[23];
    const float* badd  = (const float*)d_in[24];
    const float* Wkip  = (const float*)d_in[25];
    const float* bkip  = (const float*)d_in[26];
    const float* Wvip  = (const float*)d_in[27];
    const float* bvip  = (const float*)d_in[28];
    const float* nipq  = (const float*)d_in[29];
    const float* nipk  = (const float*)d_in[30];

    float* out = (float*)d_out;

    float* pq   = symf(g_q);   float* pk   = symf(g_k);   float* pv   = symf(g_v);
    float* peq  = symf(g_eq);  float* pek  = symf(g_ek);  float* pev  = symf(g_ev);
    float* pipk = symf(g_ipk); float* pipv = symf(g_ipv);

    __half *aqh = symh(g_aqh), *aql = symh(g_aql);
    __half *akh = symh(g_akh), *avh = symh(g_avh);

    __half *hsh = symh(g_hs_h);
    __half *ech = symh(g_enc_h);
    __half *iph_h = symh(g_iph_h);
    __half *cxh = symh(g_ctxh);
    __half *wqT = symh(g_WqT),  *wkT = symh(g_WkT),  *wvT = symh(g_WvT);
    __half *waqT = symh(g_WaqT), *wakT = symh(g_WakT), *wavT = symh(g_WavT);
    __half *woT = symh(g_WoT),  *wadT = symh(g_WadT);
    __half *wkiT = symh(g_WkiT), *wviT = symh(g_WviT);

    cudaFuncSetAttribute(gemm_mma, cudaFuncAttributeMaxDynamicSharedMemorySize, GEMM_SMEM);
    cudaFuncSetAttribute(attn_mma, cudaFuncAttributeMaxDynamicSharedMemorySize, ATTN_SMEM);

    dim3 wg(HID / 32, HID / 32, 3);
    dim3 wg2(HID / 32, HID / 32, 2);
    dim3 wgip(HID / 32, IPD / 32, 2);

    // L0, L1, L2
    conv_wT<<<wg, 256>>>(WTask{Wq, wqT}, WTask{Wk, wkT}, WTask{Wv, wvT}, HID, HID);
    conv_h<<<(S_IMG * HID / 4 + 255) / 256, 256>>>(hs, hsh, S_IMG * HID / 4);
    conv_wT<<<wg, 256>>>(WTask{Waq, waqT}, WTask{Wak, wakT}, WTask{Wav, wavT}, HID, HID);

    // L3: big img q/k/v GEMM (ncu capture slot)
    GemmSet sq{hsh, wqT, bq, pq, S_IMG, HID};
    GemmSet sk{hsh, wkT, bk, pk, S_IMG, HID};
    GemmSet sv{hsh, wvT, bv, pv, S_IMG, HID};
    gemm_mma<<<dim3(HID / 128, S_IMG / 128, 3), 256, GEMM_SMEM>>>(sq, sk, sv);

    // L4..L6
    conv_h<<<(S_TXT * HID / 4 + 255) / 256, 256>>>(enc, ech, S_TXT * HID / 4);
    conv_h<<<(LIP * IPD / 4 + 255) / 256, 256>>>(iph, iph_h, LIP * IPD / 4);
    conv_wT<<<wgip, 256>>>(WTask{Wkip, wkiT}, WTask{Wvip, wviT}, WTask{Wkip, wkiT}, IPD, HID);

    // L7: enc q/k/v GEMM
    GemmSet se1{ech, waqT, baq, peq, S_TXT, HID};
    GemmSet se2{ech, wakT, bak, pek, S_TXT, HID};
    GemmSet se3{ech, wavT, bav, pev, S_TXT, HID};
    gemm_mma<<<dim3(HID / 128, S_TXT / 128, 3), 256, GEMM_SMEM>>>(se1, se2, se3);

    // L8: ip k/v GEMM
    GemmSet si1{iph_h, wkiT, bkip, pipk, LIP, IPD};
    GemmSet si2{iph_h, wviT, bvip, pipv, LIP, IPD};
    gemm_mma<<<dim3(HID / 128, 1, 2), 256, GEMM_SMEM>>>(si1, si2, si1);

    // L9: output-projection weights
    conv_wT<<<wg2, 256>>>(WTask{Wo, woT}, WTask{Wadd, wadT}, WTask{Wo, woT}, HID, HID);

    // L10: rms + rope + head layout
    prepare_qkv<<<dim3(S_TOT, NH), 128>>>(pq, pk, pv, peq, pek, pev,
                                          nqw, nkw, naqw, nakw, rcos, rsin,
                                          aqh, aql, akh, avh);

    // L11, L12: attention (writes fp16 ctx hi), IP attention (RMW)
    attn_mma<<<dim3(S_TOT / 128, NH), 256, ATTN_SMEM>>>(aqh, aql, akh, avh, cxh);
    ip_attn<<<dim3(S_IMG / 8, NH), 256>>>(pq, pipk, pipv, nipq, nipk, cxh);

    // L13: merged output GEMMs (z=0: img via Wo, z=1: enc via Wadd)
    GemmSet so{cxh + (size_t)S_TXT * HID, woT, bo, out, S_IMG, HID};
    GemmSet sa{cxh, wadT, badd, out + (size_t)S_IMG * HID, S_TXT, HID};
    gemm_mma<<<dim3(HID / 128, S_IMG / 128, 2), 256, GEMM_SMEM>>>(so, sa, so);
}